// round 4
// baseline (speedup 1.0000x reference)
#include <cuda_runtime.h>

// ---------------------------------------------------------------------------
// GCN_81776177316393
//   feats = relu(conv1d(x, conv_w, pad=1)) : [4,3,512,2048]
//   a     = row_norm(max(adj,adj^T)+I)     : [4,256,256]
//   h     = relu(a @ (nodes@W1) + b1)
//   out   = a @ (h@W2) + b2                : [4,256,2048]
// Output buffer = feats (12,582,912 floats) ++ out (2,097,152 floats)
// ---------------------------------------------------------------------------

#define BM 128
#define BN 128
#define BK 16
#define APAD 4

typedef unsigned long long ull;

__device__ __forceinline__ ull pack2(float lo, float hi) {
    ull r; asm("mov.b64 %0, {%1, %2};" : "=l"(r) : "f"(lo), "f"(hi)); return r;
}
__device__ __forceinline__ void fma2(ull& d, ull a, ull b) {
    asm("fma.rn.f32x2 %0, %1, %2, %0;" : "+l"(d) : "l"(a), "l"(b));
}
__device__ __forceinline__ float2 unpack2(ull v) {
    float2 f; asm("mov.b64 {%0, %1}, %2;" : "=f"(f.x), "=f"(f.y) : "l"(v)); return f;
}

// Scratch (static device globals; no runtime allocation)
__device__ float g_wt[3u * 2048u * 2048u];   // w_t[k][ci][co], 48 MB
__device__ float g_anorm[4 * 256 * 256];     // normalized adjacency
__device__ float g_h1[4 * 256 * 2048];       // ping
__device__ float g_h2[4 * 256 * 2048];       // pong

// ---------------------------------------------------------------------------
// conv_w [co][ci][k] (k fastest)  ->  g_wt[k*2048+ci][co]
// 32x32 smem tile transpose of the 2048 x 6144 matrix S[co][j], j = ci*3+k,
// with dest row r(j) = (j%3)*2048 + j/3. Coalesced both directions.
// ---------------------------------------------------------------------------
__global__ void transpose_w_kernel(const float* __restrict__ w) {
    __shared__ float tile[32][33];
    int j0 = blockIdx.x * 32;
    int c0 = blockIdx.y * 32;
    int tx = threadIdx.x;
    int ty = threadIdx.y;
#pragma unroll
    for (int yy = 0; yy < 4; yy++) {
        int co = c0 + ty + yy * 8;
        tile[ty + yy * 8][tx] = w[(size_t)co * 6144 + j0 + tx];
    }
    __syncthreads();
#pragma unroll
    for (int yy = 0; yy < 4; yy++) {
        int jl = ty + yy * 8;
        int j = j0 + jl;
        int r = (j % 3) * 2048 + (j / 3);
        g_wt[(size_t)r * 2048 + c0 + tx] = tile[tx][jl];
    }
}

// ---------------------------------------------------------------------------
// a = max(adj, adj^T) + I, then row-normalize. One block per (b, row).
// ---------------------------------------------------------------------------
__global__ void norm_adj_kernel(const float* __restrict__ adj) {
    int b = blockIdx.x >> 8;
    int i = blockIdx.x & 255;
    int t = threadIdx.x;
    const float* ab = adj + (size_t)b * 65536;
    float v = fmaxf(ab[i * 256 + t], ab[t * 256 + i]) + (t == i ? 1.0f : 0.0f);
    __shared__ float red[256];
    red[t] = v;
    __syncthreads();
#pragma unroll
    for (int s = 128; s > 0; s >>= 1) {
        if (t < s) red[t] += red[t + s];
        __syncthreads();
    }
    float rs = red[0];
    float inv = rs > 0.0f ? 1.0f / rs : 0.0f;
    g_anorm[(size_t)b * 65536 + i * 256 + t] = v * inv;
}

// ---------------------------------------------------------------------------
// Tiled SGEMM, 128x128x16, 256 threads, 8x8 per thread, double-buffered smem,
// packed fp32x2 FFMA2 accumulation (2x fp32 rate on sm_103a, exact fp32).
// CONV=true: A is the im2col view of x [12][512][2048]; each BK-tile lies in
// a single conv tap k (2048 % BK == 0), with zero-padding at t = -1 / 512.
// Batched via blockIdx.z with element strides sA/sB/sC.
// ---------------------------------------------------------------------------
template <bool CONV>
__global__ void __launch_bounds__(256, 2)
gemm_kernel(const float* __restrict__ A, size_t sA,
            const float* __restrict__ B, size_t sB,
            float* __restrict__ C, size_t sC,
            const float* __restrict__ bias, int do_relu,
            int M, int N, int K)
{
    A += (size_t)blockIdx.z * sA;
    B += (size_t)blockIdx.z * sB;
    C += (size_t)blockIdx.z * sC;
    const int bm = blockIdx.y * BM;
    const int bn = blockIdx.x * BN;

    __shared__ float As[2][BK][BM + APAD];   // stored transposed: As[k][m]
    __shared__ float Bs[2][BK][BN];

    const int tid = threadIdx.x;
    const int tx = tid & 15;                 // 16 col-threads
    const int ty = tid >> 4;                 // 16 row-threads

    // A loader: 128 rows x 16 cols = 512 float4, 2 per thread (rows r, r+64)
    const int a_r = tid >> 2;
    const int a_c = (tid & 3) * 4;
    // B loader: 16 rows x 128 cols = 512 float4, 2 per thread (rows r, r+8)
    const int b_r = tid >> 5;
    const int b_c = (tid & 31) * 4;

    // conv row decomposition (all 128 rows of a block share one batch index
    // because bm % 512 in {0,128,256,384})
    int cb = 0, ct0 = 0;
    if (CONV) {
        int m0 = bm + a_r;
        cb = m0 >> 9;        // (N*n) index, 0..11
        ct0 = m0 & 511;      // t
    }

    ull acc[8][4];
#pragma unroll
    for (int i = 0; i < 8; i++)
#pragma unroll
        for (int j = 0; j < 4; j++) acc[i][j] = 0ull;

    float4 ra0, ra1, rb0, rb1;

    auto load_tiles = [&](int kt) {
        if (CONV) {
            int kc = kt >> 11;                 // conv tap 0..2
            int ci = (kt & 2047) + a_c;        // input channel
            int ts0 = ct0 - 1 + kc;
            int ts1 = ts0 + 64;
            const float* xb = A + (size_t)cb * (512 * 2048) + ci;
            ra0 = ((unsigned)ts0 < 512u) ? *(const float4*)(xb + (size_t)ts0 * 2048)
                                         : make_float4(0.f, 0.f, 0.f, 0.f);
            ra1 = ((unsigned)ts1 < 512u) ? *(const float4*)(xb + (size_t)ts1 * 2048)
                                         : make_float4(0.f, 0.f, 0.f, 0.f);
        } else {
            ra0 = *(const float4*)(A + (size_t)(bm + a_r) * K + kt + a_c);
            ra1 = *(const float4*)(A + (size_t)(bm + a_r + 64) * K + kt + a_c);
        }
        rb0 = *(const float4*)(B + (size_t)(kt + b_r) * N + bn + b_c);
        rb1 = *(const float4*)(B + (size_t)(kt + b_r + 8) * N + bn + b_c);
    };

    auto store_tiles = [&](int buf) {
        As[buf][a_c + 0][a_r] = ra0.x;
        As[buf][a_c + 1][a_r] = ra0.y;
        As[buf][a_c + 2][a_r] = ra0.z;
        As[buf][a_c + 3][a_r] = ra0.w;
        As[buf][a_c + 0][a_r + 64] = ra1.x;
        As[buf][a_c + 1][a_r + 64] = ra1.y;
        As[buf][a_c + 2][a_r + 64] = ra1.z;
        As[buf][a_c + 3][a_r + 64] = ra1.w;
        *(float4*)&Bs[buf][b_r][b_c] = rb0;
        *(float4*)&Bs[buf][b_r + 8][b_c] = rb1;
    };

    auto compute = [&](int buf) {
#pragma unroll
        for (int k = 0; k < BK; k++) {
            float4 a0 = *(const float4*)&As[buf][k][ty * 8];
            float4 a1 = *(const float4*)&As[buf][k][ty * 8 + 4];
            float4 b0 = *(const float4*)&Bs[buf][k][tx * 8];
            float4 b1 = *(const float4*)&Bs[buf][k][tx * 8 + 4];
            ull bp0 = pack2(b0.x, b0.y);
            ull bp1 = pack2(b0.z, b0.w);
            ull bp2 = pack2(b1.x, b1.y);
            ull bp3 = pack2(b1.z, b1.w);
            float av[8] = {a0.x, a0.y, a0.z, a0.w, a1.x, a1.y, a1.z, a1.w};
#pragma unroll
            for (int i = 0; i < 8; i++) {
                ull ap = pack2(av[i], av[i]);
                fma2(acc[i][0], ap, bp0);
                fma2(acc[i][1], ap, bp1);
                fma2(acc[i][2], ap, bp2);
                fma2(acc[i][3], ap, bp3);
            }
        }
    };

    load_tiles(0);
    store_tiles(0);
    __syncthreads();
    int buf = 0;
    for (int kt = BK;; kt += BK) {
        bool more = kt < K;
        if (more) load_tiles(kt);            // LDGs in flight during compute
        compute(buf);
        if (!more) break;
        store_tiles(buf ^ 1);
        __syncthreads();
        buf ^= 1;
    }

    float bv[8];
#pragma unroll
    for (int j = 0; j < 8; j++) bv[j] = bias ? bias[bn + tx * 8 + j] : 0.0f;

#pragma unroll
    for (int i = 0; i < 8; i++) {
        float o[8];
        float2 p;
        p = unpack2(acc[i][0]); o[0] = p.x + bv[0]; o[1] = p.y + bv[1];
        p = unpack2(acc[i][1]); o[2] = p.x + bv[2]; o[3] = p.y + bv[3];
        p = unpack2(acc[i][2]); o[4] = p.x + bv[4]; o[5] = p.y + bv[5];
        p = unpack2(acc[i][3]); o[6] = p.x + bv[6]; o[7] = p.y + bv[7];
        if (do_relu) {
#pragma unroll
            for (int j = 0; j < 8; j++) o[j] = fmaxf(o[j], 0.0f);
        }
        size_t off = (size_t)(bm + ty * 8 + i) * N + bn + tx * 8;
        *(float4*)(C + off)     = make_float4(o[0], o[1], o[2], o[3]);
        *(float4*)(C + off + 4) = make_float4(o[4], o[5], o[6], o[7]);
    }
}

// ---------------------------------------------------------------------------
extern "C" void kernel_launch(void* const* d_in, const int* in_sizes, int n_in,
                              void* d_out, int out_size) {
    const float* x      = (const float*)d_in[0];  // [4,3,512,2048]
    const float* nodes  = (const float*)d_in[1];  // [4,256,2048]
    const float* adj    = (const float*)d_in[2];  // [4,256,256]
    const float* conv_w = (const float*)d_in[3];  // [2048,2048,3]
    const float* conv_b = (const float*)d_in[4];  // [2048]
    const float* W1     = (const float*)d_in[5];  // [2048,2048]
    const float* b1     = (const float*)d_in[6];  // [2048]
    const float* W2     = (const float*)d_in[7];  // [2048,2048]
    const float* b2     = (const float*)d_in[8];  // [2048]

    float* feats   = (float*)d_out;                          // 12,582,912
    float* gcn_out = (float*)d_out + (size_t)12 * 512 * 2048;

    float *wt, *anorm, *h1, *h2;
    cudaGetSymbolAddress((void**)&wt, g_wt);
    cudaGetSymbolAddress((void**)&anorm, g_anorm);
    cudaGetSymbolAddress((void**)&h1, g_h1);
    cudaGetSymbolAddress((void**)&h2, g_h2);

    // 1) conv weight transpose  w[co][ci][k] -> w_t[k*2048+ci][co]
    transpose_w_kernel<<<dim3(192, 64), dim3(32, 8)>>>(conv_w);
    // 2) adjacency normalization
    norm_adj_kernel<<<1024, 256>>>(adj);
    // 3) conv as implicit GEMM: M=6144, N=2048, K=6144, relu(+bias)
    gemm_kernel<true><<<dim3(16, 48, 1), 256>>>(
        x, 0, wt, 0, feats, 0, conv_b, 1, 6144, 2048, 6144);
    // 4) H1 = nodes @ W1        (M=1024, N=2048, K=2048)
    gemm_kernel<false><<<dim3(16, 8, 1), 256>>>(
        nodes, 0, W1, 0, h1, 0, nullptr, 0, 1024, 2048, 2048);
    // 5) h = relu(a @ H1 + b1)  (batched 4x: M=256, N=2048, K=256)
    gemm_kernel<false><<<dim3(16, 2, 4), 256>>>(
        anorm, 65536, h1, 524288, h2, 524288, b1, 1, 256, 2048, 256);
    // 6) H2 = h @ W2            (M=1024, N=2048, K=2048)
    gemm_kernel<false><<<dim3(16, 8, 1), 256>>>(
        h2, 0, W2, 0, h1, 0, nullptr, 0, 1024, 2048, 2048);
    // 7) out = a @ H2 + b2      (batched 4x, no relu)
    gemm_kernel<false><<<dim3(16, 2, 4), 256>>>(
        anorm, 65536, h1, 524288, gcn_out, 524288, b2, 0, 256, 2048, 256);

    (void)in_sizes; (void)n_in; (void)out_size;
}

// round 9
// speedup vs baseline: 2.0562x; 2.0562x over previous
#include <cuda_runtime.h>
#include <cuda_bf16.h>
#include <cstdint>

// ===========================================================================
// GCN_81776177316393 — bf16x3-split GEMMs on mma.sync (HMMA, base sm_103 ISA;
// tcgen05 is NOT compilable under this harness: ptxas targets sm_103 plain).
//   feats = relu(conv1d(x, conv_w, pad=1)) : [4,3,512,2048]
//   a     = row_norm(max(adj,adj^T)+I)     : [4,256,256]
//   h     = relu(a @ (nodes@W1) + b1)
//   out   = a @ (h@W2) + b2                : [4,256,2048]
// ===========================================================================

typedef unsigned long long ull;

// -------------------- scratch (static device globals) ----------------------
__device__ __align__(16) __nv_bfloat16 g_xh[12u * 512u * 2048u];
__device__ __align__(16) __nv_bfloat16 g_xl[12u * 512u * 2048u];
__device__ __align__(16) __nv_bfloat16 g_wth[2048u * 6144u];   // B^T: [co][tap*2048+ci]
__device__ __align__(16) __nv_bfloat16 g_wtl[2048u * 6144u];
__device__ __align__(16) __nv_bfloat16 g_w1h[2048u * 2048u];   // W1^T: [n][k]
__device__ __align__(16) __nv_bfloat16 g_w1l[2048u * 2048u];
__device__ __align__(16) __nv_bfloat16 g_w2h[2048u * 2048u];
__device__ __align__(16) __nv_bfloat16 g_w2l[2048u * 2048u];
__device__ __align__(16) __nv_bfloat16 g_nh[1024u * 2048u];
__device__ __align__(16) __nv_bfloat16 g_nl[1024u * 2048u];
__device__ __align__(16) __nv_bfloat16 g_hh[1024u * 2048u];
__device__ __align__(16) __nv_bfloat16 g_hl[1024u * 2048u];
__device__ float g_anorm[4 * 256 * 256];
__device__ float g_h1[1024u * 2048u];
__device__ float g_h2[1024u * 2048u];

// -------------------- PTX helpers ------------------------------------------
__device__ __forceinline__ uint32_t smem_u32(const void* p) {
    uint32_t a;
    asm("{ .reg .u64 t; cvta.to.shared.u64 t, %1; cvt.u32.u64 %0, t; }"
        : "=r"(a) : "l"(p));
    return a;
}
__device__ __forceinline__ void ldsm4(uint32_t& r0, uint32_t& r1,
                                      uint32_t& r2, uint32_t& r3, uint32_t addr) {
    asm volatile("ldmatrix.sync.aligned.m8n8.x4.shared.b16 {%0,%1,%2,%3}, [%4];"
                 : "=r"(r0), "=r"(r1), "=r"(r2), "=r"(r3) : "r"(addr));
}
__device__ __forceinline__ void mma16816(float* d, const uint32_t* a, const uint32_t* b) {
    asm volatile("mma.sync.aligned.m16n8k16.row.col.f32.bf16.bf16.f32 "
                 "{%0,%1,%2,%3}, {%4,%5,%6,%7}, {%8,%9}, {%0,%1,%2,%3};"
                 : "+f"(d[0]), "+f"(d[1]), "+f"(d[2]), "+f"(d[3])
                 : "r"(a[0]), "r"(a[1]), "r"(a[2]), "r"(a[3]), "r"(b[0]), "r"(b[1]));
}

// -------------------- preprocessing kernels --------------------------------
__global__ void split_kernel(const float* __restrict__ s, __nv_bfloat16* __restrict__ h,
                             __nv_bfloat16* __restrict__ l, int n) {
    int i = blockIdx.x * blockDim.x + threadIdx.x;
    int stride = gridDim.x * blockDim.x;
    for (; i < n; i += stride) {
        float v = s[i];
        __nv_bfloat16 hv = __float2bfloat16(v);
        h[i] = hv;
        l[i] = __float2bfloat16(v - __bfloat162float(hv));
    }
}

// conv_w[co][ci][tap] -> g_wth/g_wtl [co][tap*2048+ci]  (smem-staged, coalesced)
__global__ void convw_split_kernel(const float* __restrict__ w) {
    __shared__ float row[6144];
    int co = blockIdx.x;
    const float* src = w + (size_t)co * 6144;
    for (int j = threadIdx.x; j < 6144; j += 256) row[j] = src[j];
    __syncthreads();
    size_t base = (size_t)co * 6144;
    for (int kk = threadIdx.x; kk < 6144; kk += 256) {
        int tap = kk >> 11, ci = kk & 2047;
        float v = row[ci * 3 + tap];
        __nv_bfloat16 hv = __float2bfloat16(v);
        g_wth[base + kk] = hv;
        g_wtl[base + kk] = __float2bfloat16(v - __bfloat162float(hv));
    }
}

// W[k][n] -> out_hi/lo [n][k]  (32x32 smem transpose + split)
__global__ void transw_split_kernel(const float* __restrict__ W,
                                    __nv_bfloat16* __restrict__ oh,
                                    __nv_bfloat16* __restrict__ ol) {
    __shared__ float tile[32][33];
    int n0 = blockIdx.x * 32, k0 = blockIdx.y * 32;
    int tx = threadIdx.x, ty = threadIdx.y;
#pragma unroll
    for (int yy = 0; yy < 4; yy++)
        tile[ty + yy * 8][tx] = W[(size_t)(k0 + ty + yy * 8) * 2048 + n0 + tx];
    __syncthreads();
#pragma unroll
    for (int yy = 0; yy < 4; yy++) {
        float v = tile[tx][ty + yy * 8];
        size_t o = (size_t)(n0 + ty + yy * 8) * 2048 + k0 + tx;
        __nv_bfloat16 hv = __float2bfloat16(v);
        oh[o] = hv;
        ol[o] = __float2bfloat16(v - __bfloat162float(hv));
    }
}

// a = max(adj, adj^T) + I, row-normalized
__global__ void norm_adj_kernel(const float* __restrict__ adj) {
    int b = blockIdx.x >> 8;
    int i = blockIdx.x & 255;
    int t = threadIdx.x;
    const float* ab = adj + (size_t)b * 65536;
    float v = fmaxf(ab[i * 256 + t], ab[t * 256 + i]) + (t == i ? 1.0f : 0.0f);
    __shared__ float red[256];
    red[t] = v;
    __syncthreads();
#pragma unroll
    for (int s = 128; s > 0; s >>= 1) {
        if (t < s) red[t] += red[t + s];
        __syncthreads();
    }
    float rs = red[0];
    float inv = rs > 0.0f ? 1.0f / rs : 0.0f;
    g_anorm[(size_t)b * 65536 + i * 256 + t] = v * inv;
}

// -------------------- HMMA bf16x3 GEMM -------------------------------------
// C[M,N] = A[M,K] @ B^T[N,K] (+bias, optional relu), fp32 via hi/lo bf16,
// 3 split terms accumulated into shared fp32 register accumulators.
// Tile: BM=128, BN=128, BK=32. 256 threads, 8 warps = 2(M) x 4(N), warp 64x32.
// Smem rows skewed to 80B stride -> conflict-free ldmatrix phases.
// CONV=true: A is im2col of x[12][512][2048]; chunk kt -> tap = kt>>11.
#define MM_STAGE 40960                       // 4 tiles * 128 rows * 80B
#define MM_SMEM  (2 * MM_STAGE)
#define OA_L 10240
#define OB_H 20480
#define OB_L 30720

template <bool CONV>
__global__ void __launch_bounds__(256, 1)
mma_gemm(const __nv_bfloat16* __restrict__ Ah, const __nv_bfloat16* __restrict__ Al,
         const __nv_bfloat16* __restrict__ Bh, const __nv_bfloat16* __restrict__ Bl,
         float* __restrict__ C, const float* __restrict__ bias, int relu,
         int K, int N)
{
    extern __shared__ __align__(128) char smem[];
    const uint32_t sbase = smem_u32(smem);
    const int tid  = threadIdx.x;
    const int lane = tid & 31;
    const int wid  = tid >> 5;
    const int bm = blockIdx.y * 128;
    const int bn = blockIdx.x * 128;
    const int wm = (wid & 1) * 64;           // warp M offset
    const int wn = (wid >> 1) * 32;          // warp N offset

    // ldmatrix per-lane base offsets (bytes), row stride 80
    uint32_t aoff[4];
#pragma unroll
    for (int mt = 0; mt < 4; mt++)
        aoff[mt] = (uint32_t)(wm + mt * 16 + (lane & 15)) * 80 + ((lane >> 4) * 16);
    const uint32_t boff = (uint32_t)(wn + lane) * 80;

    float acc[4][4][4];
#pragma unroll
    for (int i = 0; i < 4; i++)
#pragma unroll
        for (int j = 0; j < 4; j++)
#pragma unroll
            for (int r = 0; r < 4; r++) acc[i][j][r] = 0.0f;

    uint4 rAh[2], rAl[2], rBh[2], rBl[2];

    auto load_tiles = [&](int kt) {
        int tap = 0, ci0 = 0;
        if (CONV) { tap = kt >> 11; ci0 = kt & 2047; }
#pragma unroll
        for (int it = 0; it < 2; it++) {
            int i = tid + it * 256;
            int row = i >> 2, cb = (i & 3) * 8;
            if (CONV) {
                int m = bm + row;
                int b = m >> 9;
                int t = (m & 511) - 1 + tap;
                bool ok = ((unsigned)t < 512u);
                size_t go = ((size_t)b * 512 + (ok ? t : 0)) * 2048 + ci0 + cb;
                if (ok) {
                    rAh[it] = *(const uint4*)(Ah + go);
                    rAl[it] = *(const uint4*)(Al + go);
                } else {
                    rAh[it] = make_uint4(0, 0, 0, 0);
                    rAl[it] = make_uint4(0, 0, 0, 0);
                }
            } else {
                size_t go = (size_t)(bm + row) * K + kt + cb;
                rAh[it] = *(const uint4*)(Ah + go);
                rAl[it] = *(const uint4*)(Al + go);
            }
            size_t gb = (size_t)(bn + row) * K + kt + cb;
            rBh[it] = *(const uint4*)(Bh + gb);
            rBl[it] = *(const uint4*)(Bl + gb);
        }
    };
    auto store_tiles = [&](int buf) {
        char* st = smem + buf * MM_STAGE;
#pragma unroll
        for (int it = 0; it < 2; it++) {
            int i = tid + it * 256;
            uint32_t off = (uint32_t)(i >> 2) * 80 + (i & 3) * 16;
            *(uint4*)(st + off)        = rAh[it];
            *(uint4*)(st + OA_L + off) = rAl[it];
            *(uint4*)(st + OB_H + off) = rBh[it];
            *(uint4*)(st + OB_L + off) = rBl[it];
        }
    };
    auto compute = [&](int buf) {
        uint32_t sb = sbase + buf * MM_STAGE;
#pragma unroll
        for (int h = 0; h < 2; h++) {
            uint32_t hb = (uint32_t)h * 32;
            uint32_t fah[4][4], fal[4][4], fbh[4][2], fbl[4][2];
#pragma unroll
            for (int mt = 0; mt < 4; mt++) {
                ldsm4(fah[mt][0], fah[mt][1], fah[mt][2], fah[mt][3],
                      sb + aoff[mt] + hb);
                ldsm4(fal[mt][0], fal[mt][1], fal[mt][2], fal[mt][3],
                      sb + OA_L + aoff[mt] + hb);
            }
            ldsm4(fbh[0][0], fbh[1][0], fbh[2][0], fbh[3][0], sb + OB_H + boff + hb);
            ldsm4(fbh[0][1], fbh[1][1], fbh[2][1], fbh[3][1], sb + OB_H + boff + hb + 16);
            ldsm4(fbl[0][0], fbl[1][0], fbl[2][0], fbl[3][0], sb + OB_L + boff + hb);
            ldsm4(fbl[0][1], fbl[1][1], fbl[2][1], fbl[3][1], sb + OB_L + boff + hb + 16);
#pragma unroll
            for (int mt = 0; mt < 4; mt++)
#pragma unroll
                for (int nt = 0; nt < 4; nt++) {
                    mma16816(acc[mt][nt], fah[mt], fbh[nt]);   // hi*hi
                    mma16816(acc[mt][nt], fah[mt], fbl[nt]);   // hi*lo
                    mma16816(acc[mt][nt], fal[mt], fbh[nt]);   // lo*hi
                }
        }
    };

    load_tiles(0);
    store_tiles(0);
    __syncthreads();
    int buf = 0;
    for (int kt = 32;; kt += 32) {
        bool more = kt < K;
        if (more) load_tiles(kt);
        compute(buf);
        if (!more) break;
        store_tiles(buf ^ 1);
        __syncthreads();
        buf ^= 1;
    }

    // epilogue: c0,c1 -> (row, col..col+1); c2,c3 -> (row+8, ...)
    const int r0 = lane >> 2, cp = (lane & 3) * 2;
#pragma unroll
    for (int mt = 0; mt < 4; mt++) {
        int row = bm + wm + mt * 16 + r0;
#pragma unroll
        for (int nt = 0; nt < 4; nt++) {
            int col = bn + wn + nt * 8 + cp;
            float b0 = bias ? __ldg(bias + col) : 0.0f;
            float b1 = bias ? __ldg(bias + col + 1) : 0.0f;
            float o0 = acc[mt][nt][0] + b0, o1 = acc[mt][nt][1] + b1;
            float o2 = acc[mt][nt][2] + b0, o3 = acc[mt][nt][3] + b1;
            if (relu) {
                o0 = fmaxf(o0, 0.f); o1 = fmaxf(o1, 0.f);
                o2 = fmaxf(o2, 0.f); o3 = fmaxf(o3, 0.f);
            }
            *(float2*)(C + (size_t)row * N + col)       = make_float2(o0, o1);
            *(float2*)(C + (size_t)(row + 8) * N + col) = make_float2(o2, o3);
        }
    }
}

// -------------------- FFMA2 GEMM (small batched a@H) ------------------------
#define BM 128
#define BN 128
#define BK 16
#define APAD 4

__device__ __forceinline__ ull pack2(float lo, float hi) {
    ull r; asm("mov.b64 %0, {%1, %2};" : "=l"(r) : "f"(lo), "f"(hi)); return r;
}
__device__ __forceinline__ void fma2(ull& d, ull a, ull b) {
    asm("fma.rn.f32x2 %0, %1, %2, %0;" : "+l"(d) : "l"(a), "l"(b));
}
__device__ __forceinline__ float2 unpack2(ull v) {
    float2 f; asm("mov.b64 {%0, %1}, %2;" : "=f"(f.x), "=f"(f.y) : "l"(v)); return f;
}

__global__ void __launch_bounds__(256, 2)
ffma_gemm(const float* __restrict__ A, size_t sA,
          const float* __restrict__ B, size_t sB,
          float* __restrict__ C, size_t sC,
          const float* __restrict__ bias, int do_relu,
          int M, int N, int K)
{
    A += (size_t)blockIdx.z * sA;
    B += (size_t)blockIdx.z * sB;
    C += (size_t)blockIdx.z * sC;
    const int bm = blockIdx.y * BM;
    const int bn = blockIdx.x * BN;

    __shared__ float As[2][BK][BM + APAD];
    __shared__ float Bs[2][BK][BN];

    const int tid = threadIdx.x;
    const int tx = tid & 15;
    const int ty = tid >> 4;
    const int a_r = tid >> 2;
    const int a_c = (tid & 3) * 4;
    const int b_r = tid >> 5;
    const int b_c = (tid & 31) * 4;

    ull acc[8][4];
#pragma unroll
    for (int i = 0; i < 8; i++)
#pragma unroll
        for (int j = 0; j < 4; j++) acc[i][j] = 0ull;

    float4 ra0, ra1, rb0, rb1;

    auto load_tiles = [&](int kt) {
        ra0 = *(const float4*)(A + (size_t)(bm + a_r) * K + kt + a_c);
        ra1 = *(const float4*)(A + (size_t)(bm + a_r + 64) * K + kt + a_c);
        rb0 = *(const float4*)(B + (size_t)(kt + b_r) * N + bn + b_c);
        rb1 = *(const float4*)(B + (size_t)(kt + b_r + 8) * N + bn + b_c);
    };
    auto store_tiles = [&](int buf) {
        As[buf][a_c + 0][a_r] = ra0.x; As[buf][a_c + 1][a_r] = ra0.y;
        As[buf][a_c + 2][a_r] = ra0.z; As[buf][a_c + 3][a_r] = ra0.w;
        As[buf][a_c + 0][a_r + 64] = ra1.x; As[buf][a_c + 1][a_r + 64] = ra1.y;
        As[buf][a_c + 2][a_r + 64] = ra1.z; As[buf][a_c + 3][a_r + 64] = ra1.w;
        *(float4*)&Bs[buf][b_r][b_c] = rb0;
        *(float4*)&Bs[buf][b_r + 8][b_c] = rb1;
    };
    auto compute = [&](int buf) {
#pragma unroll
        for (int k = 0; k < BK; k++) {
            float4 a0 = *(const float4*)&As[buf][k][ty * 8];
            float4 a1 = *(const float4*)&As[buf][k][ty * 8 + 4];
            float4 b0 = *(const float4*)&Bs[buf][k][tx * 8];
            float4 b1 = *(const float4*)&Bs[buf][k][tx * 8 + 4];
            ull bp0 = pack2(b0.x, b0.y), bp1 = pack2(b0.z, b0.w);
            ull bp2 = pack2(b1.x, b1.y), bp3 = pack2(b1.z, b1.w);
            float av[8] = {a0.x, a0.y, a0.z, a0.w, a1.x, a1.y, a1.z, a1.w};
#pragma unroll
            for (int i = 0; i < 8; i++) {
                ull ap = pack2(av[i], av[i]);
                fma2(acc[i][0], ap, bp0); fma2(acc[i][1], ap, bp1);
                fma2(acc[i][2], ap, bp2); fma2(acc[i][3], ap, bp3);
            }
        }
    };

    load_tiles(0);
    store_tiles(0);
    __syncthreads();
    int buf = 0;
    for (int kt = BK;; kt += BK) {
        bool more = kt < K;
        if (more) load_tiles(kt);
        compute(buf);
        if (!more) break;
        store_tiles(buf ^ 1);
        __syncthreads();
        buf ^= 1;
    }

    float bv[8];
#pragma unroll
    for (int j = 0; j < 8; j++) bv[j] = bias ? bias[bn + tx * 8 + j] : 0.0f;

#pragma unroll
    for (int i = 0; i < 8; i++) {
        float o[8];
        float2 p;
        p = unpack2(acc[i][0]); o[0] = p.x + bv[0]; o[1] = p.y + bv[1];
        p = unpack2(acc[i][1]); o[2] = p.x + bv[2]; o[3] = p.y + bv[3];
        p = unpack2(acc[i][2]); o[4] = p.x + bv[4]; o[5] = p.y + bv[5];
        p = unpack2(acc[i][3]); o[6] = p.x + bv[6]; o[7] = p.y + bv[7];
        if (do_relu) {
#pragma unroll
            for (int j = 0; j < 8; j++) o[j] = fmaxf(o[j], 0.0f);
        }
        size_t off = (size_t)(bm + ty * 8 + i) * N + bn + tx * 8;
        *(float4*)(C + off)     = make_float4(o[0], o[1], o[2], o[3]);
        *(float4*)(C + off + 4) = make_float4(o[4], o[5], o[6], o[7]);
    }
}

// ---------------------------------------------------------------------------
extern "C" void kernel_launch(void* const* d_in, const int* in_sizes, int n_in,
                              void* d_out, int out_size) {
    const float* x      = (const float*)d_in[0];
    const float* nodes  = (const float*)d_in[1];
    const float* adj    = (const float*)d_in[2];
    const float* conv_w = (const float*)d_in[3];
    const float* conv_b = (const float*)d_in[4];
    const float* W1     = (const float*)d_in[5];
    const float* b1     = (const float*)d_in[6];
    const float* W2     = (const float*)d_in[7];
    const float* b2     = (const float*)d_in[8];

    float* feats   = (float*)d_out;
    float* gcn_out = (float*)d_out + (size_t)12 * 512 * 2048;

    __nv_bfloat16 *xh, *xl, *wth, *wtl, *w1h, *w1l, *w2h, *w2l, *nh, *nl, *hh, *hl;
    float *anorm, *h1, *h2;
    cudaGetSymbolAddress((void**)&xh, g_xh);   cudaGetSymbolAddress((void**)&xl, g_xl);
    cudaGetSymbolAddress((void**)&wth, g_wth); cudaGetSymbolAddress((void**)&wtl, g_wtl);
    cudaGetSymbolAddress((void**)&w1h, g_w1h); cudaGetSymbolAddress((void**)&w1l, g_w1l);
    cudaGetSymbolAddress((void**)&w2h, g_w2h); cudaGetSymbolAddress((void**)&w2l, g_w2l);
    cudaGetSymbolAddress((void**)&nh, g_nh);   cudaGetSymbolAddress((void**)&nl, g_nl);
    cudaGetSymbolAddress((void**)&hh, g_hh);   cudaGetSymbolAddress((void**)&hl, g_hl);
    cudaGetSymbolAddress((void**)&anorm, g_anorm);
    cudaGetSymbolAddress((void**)&h1, g_h1);   cudaGetSymbolAddress((void**)&h2, g_h2);

    cudaFuncSetAttribute((const void*)mma_gemm<true>,
                         cudaFuncAttributeMaxDynamicSharedMemorySize, MM_SMEM);
    cudaFuncSetAttribute((const void*)mma_gemm<false>,
                         cudaFuncAttributeMaxDynamicSharedMemorySize, MM_SMEM);

    // preprocessing: bf16 hi/lo splits + transposes
    convw_split_kernel<<<2048, 256>>>(conv_w);
    split_kernel<<<4096, 256>>>(x, xh, xl, 12 * 512 * 2048);
    transw_split_kernel<<<dim3(64, 64), dim3(32, 8)>>>(W1, w1h, w1l);
    transw_split_kernel<<<dim3(64, 64), dim3(32, 8)>>>(W2, w2h, w2l);
    split_kernel<<<2048, 256>>>(nodes, nh, nl, 1024 * 2048);
    norm_adj_kernel<<<1024, 256>>>(adj);

    // conv1d as implicit GEMM: M=6144, N=2048, K=6144, relu(+bias)
    mma_gemm<true><<<dim3(16, 48), 256, MM_SMEM>>>(
        xh, xl, wth, wtl, feats, conv_b, 1, 6144, 2048);
    // H1 = nodes @ W1 : M=1024, N=2048, K=2048
    mma_gemm<false><<<dim3(16, 8), 256, MM_SMEM>>>(
        nh, nl, w1h, w1l, h1, nullptr, 0, 2048, 2048);
    // h = relu(a @ H1 + b1) : batched 4x [256,2048,256] (exact fp32)
    ffma_gemm<<<dim3(16, 2, 4), 256>>>(
        anorm, 65536, h1, 524288, h2, 524288, b1, 1, 256, 2048, 256);
    // split h for tensor path
    split_kernel<<<2048, 256>>>(h2, hh, hl, 1024 * 2048);
    // H2 = h @ W2 : M=1024, N=2048, K=2048
    mma_gemm<false><<<dim3(16, 8), 256, MM_SMEM>>>(
        hh, hl, w2h, w2l, h1, nullptr, 0, 2048, 2048);
    // out = a @ H2 + b2 : batched 4x, no relu
    ffma_gemm<<<dim3(16, 2, 4), 256>>>(
        anorm, 65536, h1, 524288, gcn_out, 524288, b2, 0, 256, 2048, 256);

    (void)in_sizes; (void)n_in; (void)out_size;
}